// round 5
// baseline (speedup 1.0000x reference)
#include <cuda_runtime.h>
#include <math_constants.h>

// Single-query attention: y = softmax(K @ q) @ V   (fp32, M=131072, D=256)
// Single fused kernel. 2048 CTAs x 256 thr, 8 rows/warp: batched K loads ->
// logits in regs; batched V loads -> weighted acc. Lower register pressure
// (R4 showed occ=43.7% @51 regs capped BW at 5.2TB/s). __ldcs streaming
// loads (single-pass 256MB, no L2 reuse). Two-level last-arriver combine.

#define M_TOTAL   131072
#define DIM       256
#define NUM_CTAS  2048
#define ROWS_PER_CTA (M_TOTAL / NUM_CTAS)     // 64
#define NWARPS    8
#define ROWS_PER_WARP (ROWS_PER_CTA / NWARPS) // 8
#define RB        4                            // row batch

#define NGROUPS   64
#define GROUP_SZ  (NUM_CTAS / NGROUPS)        // 32

// Scratch (allocation-free): ~2.2 MB
__device__ float g_part[NUM_CTAS][DIM];
__device__ float g_m[NUM_CTAS];
__device__ float g_l[NUM_CTAS];
__device__ float g_part2[NGROUPS][DIM];
__device__ float g_m2[NGROUPS];
__device__ float g_l2[NGROUPS];
__device__ unsigned int g_cnt1[NGROUPS];  // zero-init; reset by final combiner
__device__ unsigned int g_cnt2;

__global__ __launch_bounds__(256)
void sqa_fused(const float* __restrict__ q,
               const float* __restrict__ K,
               const float* __restrict__ V,
               float* __restrict__ out) {
    const int tid  = threadIdx.x;
    const int warp = tid >> 5;
    const int lane = tid & 31;
    const int bid  = blockIdx.x;

    const float4 q0 = reinterpret_cast<const float4*>(q)[lane];
    const float4 q1 = reinterpret_cast<const float4*>(q)[lane + 32];

    const int row0 = bid * ROWS_PER_CTA + warp * ROWS_PER_WARP;

    // ---------------- Phase A: K stream -> 8 logits in registers ----------
    float d[ROWS_PER_WARP];

    #pragma unroll
    for (int rb = 0; rb < ROWS_PER_WARP; rb += RB) {
        float4 k0[RB], k1[RB];
        #pragma unroll
        for (int j = 0; j < RB; ++j) {
            const float4* Kr =
                reinterpret_cast<const float4*>(K + (size_t)(row0 + rb + j) * DIM);
            k0[j] = __ldcs(Kr + lane);
            k1[j] = __ldcs(Kr + lane + 32);
        }
        #pragma unroll
        for (int j = 0; j < RB; ++j) {
            float v = k0[j].x * q0.x + k0[j].y * q0.y + k0[j].z * q0.z + k0[j].w * q0.w
                    + k1[j].x * q1.x + k1[j].y * q1.y + k1[j].z * q1.z + k1[j].w * q1.w;
            #pragma unroll
            for (int off = 16; off > 0; off >>= 1)
                v += __shfl_xor_sync(0xffffffffu, v, off);
            d[rb + j] = v;
        }
    }

    float m = d[0];
    #pragma unroll
    for (int r = 1; r < ROWS_PER_WARP; ++r) m = fmaxf(m, d[r]);
    float w[ROWS_PER_WARP];
    float l = 0.0f;
    #pragma unroll
    for (int r = 0; r < ROWS_PER_WARP; ++r) { w[r] = __expf(d[r] - m); l += w[r]; }

    // ---------------- Phase B: V stream -> weighted accumulation ----------
    float4 a0 = make_float4(0.f, 0.f, 0.f, 0.f);
    float4 a1 = make_float4(0.f, 0.f, 0.f, 0.f);

    #pragma unroll
    for (int rb = 0; rb < ROWS_PER_WARP; rb += RB) {
        float4 v0[RB], v1[RB];
        #pragma unroll
        for (int j = 0; j < RB; ++j) {
            const float4* Vr =
                reinterpret_cast<const float4*>(V + (size_t)(row0 + rb + j) * DIM);
            v0[j] = __ldcs(Vr + lane);
            v1[j] = __ldcs(Vr + lane + 32);
        }
        #pragma unroll
        for (int j = 0; j < RB; ++j) {
            const float wj = w[rb + j];
            a0.x += wj * v0[j].x;  a0.y += wj * v0[j].y;
            a0.z += wj * v0[j].z;  a0.w += wj * v0[j].w;
            a1.x += wj * v1[j].x;  a1.y += wj * v1[j].y;
            a1.z += wj * v1[j].z;  a1.w += wj * v1[j].w;
        }
    }

    // ---------------- Merge 8 warps within the CTA ------------------------
    __shared__ float s_m[NWARPS];
    __shared__ float s_l[NWARPS];
    __shared__ float s_acc[NWARPS][DIM];
    __shared__ unsigned int s_last;

    if (lane == 0) { s_m[warp] = m; s_l[warp] = l; }
    float* dst = s_acc[warp];
    dst[lane * 4 + 0]       = a0.x;
    dst[lane * 4 + 1]       = a0.y;
    dst[lane * 4 + 2]       = a0.z;
    dst[lane * 4 + 3]       = a0.w;
    dst[128 + lane * 4 + 0] = a1.x;
    dst[128 + lane * 4 + 1] = a1.y;
    dst[128 + lane * 4 + 2] = a1.z;
    dst[128 + lane * 4 + 3] = a1.w;
    __syncthreads();

    float bm = s_m[0];
    #pragma unroll
    for (int w2 = 1; w2 < NWARPS; ++w2) bm = fmaxf(bm, s_m[w2]);

    float y = 0.0f;
    float L = 0.0f;
    #pragma unroll
    for (int w2 = 0; w2 < NWARPS; ++w2) {
        const float sf = __expf(s_m[w2] - bm);
        y += s_acc[w2][tid] * sf;
        L += s_l[w2] * sf;
    }

    g_part[bid][tid] = y;
    if (tid == 0) { g_m[bid] = bm; g_l[bid] = L; }

    // ---------------- Level 1: last CTA of each group combines ------------
    const int grp = bid / GROUP_SZ;
    __syncthreads();
    if (tid == 0) {
        __threadfence();  // release
        s_last = (atomicAdd(&g_cnt1[grp], 1u) == GROUP_SZ - 1u);
    }
    __syncthreads();
    if (!s_last) return;
    if (tid == 0) __threadfence();  // acquire
    __syncthreads();

    {
        const int i0 = grp * GROUP_SZ;
        float gm = g_m[i0];
        #pragma unroll
        for (int j = 1; j < GROUP_SZ; ++j) gm = fmaxf(gm, g_m[i0 + j]);

        float acc = 0.0f;
        float ll  = 0.0f;
        #pragma unroll 4
        for (int j = 0; j < GROUP_SZ; ++j) {
            const float sf = __expf(g_m[i0 + j] - gm);
            acc += g_part[i0 + j][tid] * sf;
            ll  += g_l[i0 + j] * sf;
        }
        g_part2[grp][tid] = acc;
        if (tid == 0) { g_m2[grp] = gm; g_l2[grp] = ll; }
    }

    // ---------------- Level 2: last group-combiner does final -------------
    __syncthreads();
    if (tid == 0) {
        __threadfence();
        s_last = (atomicAdd(&g_cnt2, 1u) == NGROUPS - 1u);
    }
    __syncthreads();
    if (!s_last) return;
    if (tid == 0) __threadfence();
    __syncthreads();

    {
        float gm = g_m2[0];
        #pragma unroll
        for (int j = 1; j < NGROUPS; ++j) gm = fmaxf(gm, g_m2[j]);

        float acc = 0.0f;
        float ll  = 0.0f;
        #pragma unroll 4
        for (int j = 0; j < NGROUPS; ++j) {
            const float sf = __expf(g_m2[j] - gm);
            acc += g_part2[j][tid] * sf;
            ll  += g_l2[j] * sf;
        }
        out[tid] = acc / ll;
    }

    // Reset counters for next graph replay (only this CTA is alive here).
    if (tid < NGROUPS) g_cnt1[tid] = 0u;
    if (tid == 0) g_cnt2 = 0u;
}

extern "C" void kernel_launch(void* const* d_in, const int* in_sizes, int n_in,
                              void* d_out, int out_size) {
    const float* q = (const float*)d_in[0];
    const float* K = (const float*)d_in[1];
    const float* V = (const float*)d_in[2];
    float* out = (float*)d_out;

    sqa_fused<<<NUM_CTAS, 256>>>(q, K, V, out);
}

// round 6
// speedup vs baseline: 1.0111x; 1.0111x over previous
#include <cuda_runtime.h>
#include <math_constants.h>

// Single-query attention: y = softmax(K @ q) @ V   (fp32, M=131072, D=256)
// Two-kernel split. Pass1 is byte-identical to the variant measured at
// ~8.4 TB/s (every fused variant degraded the streaming loop to 4-5 TB/s).
// Tail consolidated from 3 kernels (~24us of launch latency) into ONE:
// 32 blocks each combine a group of 32 partials; last-arriver block does
// the final combine and resets the counter for graph replay.

#define M_TOTAL   131072
#define DIM       256
#define NUM_CTAS  1024
#define ROWS_PER_CTA (M_TOTAL / NUM_CTAS)     // 128
#define NWARPS    8
#define ROWS_PER_WARP (ROWS_PER_CTA / NWARPS) // 16

#define NGROUPS   32
#define GROUP_SZ  (NUM_CTAS / NGROUPS)        // 32

// Scratch (allocation-free): ~1.1 MB
__device__ float g_part[NUM_CTAS][DIM];
__device__ float g_m[NUM_CTAS];
__device__ float g_l[NUM_CTAS];
__device__ float g_part2[NGROUPS][DIM];
__device__ float g_m2[NGROUPS];
__device__ float g_l2[NGROUPS];
__device__ unsigned int g_cnt;   // zero-init; reset by final block

__global__ __launch_bounds__(256)
void sqa_pass1(const float* __restrict__ q,
               const float* __restrict__ K,
               const float* __restrict__ V) {
    const int tid  = threadIdx.x;
    const int warp = tid >> 5;
    const int lane = tid & 31;

    const float4 q0 = reinterpret_cast<const float4*>(q)[lane];
    const float4 q1 = reinterpret_cast<const float4*>(q)[lane + 32];

    const int row0 = blockIdx.x * ROWS_PER_CTA + warp * ROWS_PER_WARP;

    float m = -CUDART_INF_F;
    float l = 0.0f;
    float4 a0 = make_float4(0.f, 0.f, 0.f, 0.f);
    float4 a1 = make_float4(0.f, 0.f, 0.f, 0.f);

    #pragma unroll 2
    for (int r = 0; r < ROWS_PER_WARP; ++r) {
        const size_t row = (size_t)(row0 + r);
        const float4* Kr = reinterpret_cast<const float4*>(K + row * DIM);
        const float4* Vr = reinterpret_cast<const float4*>(V + row * DIM);

        const float4 k0 = Kr[lane];
        const float4 k1 = Kr[lane + 32];
        const float4 v0 = Vr[lane];
        const float4 v1 = Vr[lane + 32];

        float d = k0.x * q0.x + k0.y * q0.y + k0.z * q0.z + k0.w * q0.w
                + k1.x * q1.x + k1.y * q1.y + k1.z * q1.z + k1.w * q1.w;
        #pragma unroll
        for (int off = 16; off > 0; off >>= 1)
            d += __shfl_xor_sync(0xffffffffu, d, off);

        const float mnew  = fmaxf(m, d);
        const float scale = __expf(m - mnew);   // exp(-inf)=0 on first iter
        const float w     = __expf(d - mnew);
        l = l * scale + w;
        a0.x = a0.x * scale + w * v0.x;
        a0.y = a0.y * scale + w * v0.y;
        a0.z = a0.z * scale + w * v0.z;
        a0.w = a0.w * scale + w * v0.w;
        a1.x = a1.x * scale + w * v1.x;
        a1.y = a1.y * scale + w * v1.y;
        a1.z = a1.z * scale + w * v1.z;
        a1.w = a1.w * scale + w * v1.w;
        m = mnew;
    }

    __shared__ float s_m[NWARPS];
    __shared__ float s_l[NWARPS];
    __shared__ float s_acc[NWARPS][DIM];

    if (lane == 0) { s_m[warp] = m; s_l[warp] = l; }
    float* dst = s_acc[warp];
    dst[lane * 4 + 0]       = a0.x;
    dst[lane * 4 + 1]       = a0.y;
    dst[lane * 4 + 2]       = a0.z;
    dst[lane * 4 + 3]       = a0.w;
    dst[128 + lane * 4 + 0] = a1.x;
    dst[128 + lane * 4 + 1] = a1.y;
    dst[128 + lane * 4 + 2] = a1.z;
    dst[128 + lane * 4 + 3] = a1.w;
    __syncthreads();

    float bm = s_m[0];
    #pragma unroll
    for (int w2 = 1; w2 < NWARPS; ++w2) bm = fmaxf(bm, s_m[w2]);

    float y = 0.0f;
    float L = 0.0f;
    #pragma unroll
    for (int w2 = 0; w2 < NWARPS; ++w2) {
        const float sf = __expf(s_m[w2] - bm);
        y += s_acc[w2][tid] * sf;
        L += s_l[w2] * sf;
    }

    g_part[blockIdx.x][tid] = y;
    if (tid == 0) { g_m[blockIdx.x] = bm; g_l[blockIdx.x] = L; }
}

// Single tail kernel: 32 blocks; each combines its group of 32 partials,
// last-arriver block performs the final combine + counter reset.
__global__ __launch_bounds__(256)
void sqa_pass2(float* __restrict__ out) {
    const int t   = threadIdx.x;
    const int grp = blockIdx.x;
    const int i0  = grp * GROUP_SZ;

    __shared__ unsigned int s_last;

    // Level 1: group-local max + scaled sums (no global pre-pass needed)
    float gm = g_m[i0];
    #pragma unroll
    for (int j = 1; j < GROUP_SZ; ++j) gm = fmaxf(gm, g_m[i0 + j]);

    float acc = 0.0f;
    float ll  = 0.0f;
    #pragma unroll 4
    for (int j = 0; j < GROUP_SZ; ++j) {
        const float sf = __expf(g_m[i0 + j] - gm);
        acc += g_part[i0 + j][t] * sf;
        ll  += g_l[i0 + j] * sf;
    }
    g_part2[grp][t] = acc;
    if (t == 0) { g_m2[grp] = gm; g_l2[grp] = ll; }

    // Last-arriver block does the final combine
    __syncthreads();
    if (t == 0) {
        __threadfence();  // release this block's global stores
        s_last = (atomicAdd(&g_cnt, 1u) == NGROUPS - 1u);
    }
    __syncthreads();
    if (!s_last) return;
    if (t == 0) __threadfence();  // acquire other blocks' stores
    __syncthreads();

    float fm = g_m2[0];
    #pragma unroll
    for (int j = 1; j < NGROUPS; ++j) fm = fmaxf(fm, g_m2[j]);

    float facc = 0.0f;
    float fll  = 0.0f;
    #pragma unroll 4
    for (int j = 0; j < NGROUPS; ++j) {
        const float sf = __expf(g_m2[j] - fm);
        facc += g_part2[j][t] * sf;
        fll  += g_l2[j] * sf;
    }
    out[t] = facc / fll;

    // Reset counter for the next graph replay (only this block alive here).
    if (t == 0) g_cnt = 0u;
}

extern "C" void kernel_launch(void* const* d_in, const int* in_sizes, int n_in,
                              void* d_out, int out_size) {
    const float* q = (const float*)d_in[0];
    const float* K = (const float*)d_in[1];
    const float* V = (const float*)d_in[2];
    float* out = (float*)d_out;

    sqa_pass1<<<NUM_CTAS, 256>>>(q, K, V);
    sqa_pass2<<<NGROUPS, 256>>>(out);
}

// round 7
// speedup vs baseline: 1.1232x; 1.1108x over previous
#include <cuda_runtime.h>
#include <math_constants.h>

// Single-query attention: y = softmax(K @ q) @ V   (fp32, M=131072, D=256)
// Persistent single-wave pass1: grid 592 = 148 SM x 4 CTAs (launch_bounds
// guarantees 4 resident/SM => exactly one wave, no wave-quantization loss,
// which capped every prior variant at ~66% DRAM). Work striped in 32-row
// chunks (4096 chunks, static stride 592 => 1.2% imbalance, deterministic).
// Online softmax rescale across chunks. Tail: one 37-block kernel.

#define M_TOTAL   131072
#define DIM       256
#define NCTA      592                      // 148 * 4, one wave
#define NWARPS    8
#define RB        4                        // rows per warp per chunk
#define CHUNK_ROWS (NWARPS * RB)           // 32
#define NCHUNKS   (M_TOTAL / CHUNK_ROWS)   // 4096

#define NGROUPS   37                       // 592 / 16
#define GROUP_SZ  16

// Scratch (allocation-free): ~650 KB
__device__ float g_part[NCTA][DIM];
__device__ float g_m[NCTA];
__device__ float g_l[NCTA];
__device__ float g_part2[NGROUPS][DIM];
__device__ float g_m2[NGROUPS];
__device__ float g_l2[NGROUPS];
__device__ unsigned int g_cnt;   // zero-init; reset by final block

__global__ __launch_bounds__(256, 4)
void sqa_pass1(const float* __restrict__ q,
               const float* __restrict__ K,
               const float* __restrict__ V) {
    const int tid  = threadIdx.x;
    const int warp = tid >> 5;
    const int lane = tid & 31;
    const int bid  = blockIdx.x;

    const float4 q0 = reinterpret_cast<const float4*>(q)[lane];
    const float4 q1 = reinterpret_cast<const float4*>(q)[lane + 32];

    float m = -CUDART_INF_F;
    float l = 0.0f;
    float4 a0 = make_float4(0.f, 0.f, 0.f, 0.f);
    float4 a1 = make_float4(0.f, 0.f, 0.f, 0.f);

    for (int c = bid; c < NCHUNKS; c += NCTA) {
        const int row0 = c * CHUNK_ROWS + warp * RB;

        // -------- K batch: 8 independent LDG.128 --------
        float4 k0[RB], k1[RB];
        #pragma unroll
        for (int j = 0; j < RB; ++j) {
            const float4* Kr =
                reinterpret_cast<const float4*>(K + (size_t)(row0 + j) * DIM);
            k0[j] = Kr[lane];
            k1[j] = Kr[lane + 32];
        }

        float d[RB];
        #pragma unroll
        for (int j = 0; j < RB; ++j) {
            float v = k0[j].x * q0.x + k0[j].y * q0.y + k0[j].z * q0.z + k0[j].w * q0.w
                    + k1[j].x * q1.x + k1[j].y * q1.y + k1[j].z * q1.z + k1[j].w * q1.w;
            #pragma unroll
            for (int off = 16; off > 0; off >>= 1)
                v += __shfl_xor_sync(0xffffffffu, v, off);
            d[j] = v;
        }

        // -------- online softmax update (chunk granularity) --------
        float mc = fmaxf(fmaxf(d[0], d[1]), fmaxf(d[2], d[3]));
        const float mnew  = fmaxf(m, mc);
        const float scale = __expf(m - mnew);   // exp(-inf)=0 on first chunk
        float w[RB];
        #pragma unroll
        for (int j = 0; j < RB; ++j) w[j] = __expf(d[j] - mnew);
        l = l * scale + (w[0] + w[1]) + (w[2] + w[3]);
        m = mnew;

        // -------- V batch: 8 independent LDG.128, weighted accumulate -----
        float4 v0[RB], v1[RB];
        #pragma unroll
        for (int j = 0; j < RB; ++j) {
            const float4* Vr =
                reinterpret_cast<const float4*>(V + (size_t)(row0 + j) * DIM);
            v0[j] = Vr[lane];
            v1[j] = Vr[lane + 32];
        }

        a0.x *= scale; a0.y *= scale; a0.z *= scale; a0.w *= scale;
        a1.x *= scale; a1.y *= scale; a1.z *= scale; a1.w *= scale;
        #pragma unroll
        for (int j = 0; j < RB; ++j) {
            a0.x += w[j] * v0[j].x;  a0.y += w[j] * v0[j].y;
            a0.z += w[j] * v0[j].z;  a0.w += w[j] * v0[j].w;
            a1.x += w[j] * v1[j].x;  a1.y += w[j] * v1[j].y;
            a1.z += w[j] * v1[j].z;  a1.w += w[j] * v1[j].w;
        }
    }

    // ---------------- Merge 8 warps within the CTA ------------------------
    __shared__ float s_m[NWARPS];
    __shared__ float s_l[NWARPS];
    __shared__ float s_acc[NWARPS][DIM];

    if (lane == 0) { s_m[warp] = m; s_l[warp] = l; }
    float* dst = s_acc[warp];
    dst[lane * 4 + 0]       = a0.x;
    dst[lane * 4 + 1]       = a0.y;
    dst[lane * 4 + 2]       = a0.z;
    dst[lane * 4 + 3]       = a0.w;
    dst[128 + lane * 4 + 0] = a1.x;
    dst[128 + lane * 4 + 1] = a1.y;
    dst[128 + lane * 4 + 2] = a1.z;
    dst[128 + lane * 4 + 3] = a1.w;
    __syncthreads();

    float bm = s_m[0];
    #pragma unroll
    for (int w2 = 1; w2 < NWARPS; ++w2) bm = fmaxf(bm, s_m[w2]);

    float y = 0.0f;
    float L = 0.0f;
    #pragma unroll
    for (int w2 = 0; w2 < NWARPS; ++w2) {
        const float sf = __expf(s_m[w2] - bm);
        y += s_acc[w2][tid] * sf;
        L += s_l[w2] * sf;
    }

    g_part[bid][tid] = y;
    if (tid == 0) { g_m[bid] = bm; g_l[bid] = L; }
}

// Tail: 37 blocks; each combines 16 partials; last-arriver block finishes.
__global__ __launch_bounds__(256)
void sqa_pass2(float* __restrict__ out) {
    const int t   = threadIdx.x;
    const int grp = blockIdx.x;
    const int i0  = grp * GROUP_SZ;

    __shared__ unsigned int s_last;

    float gm = g_m[i0];
    #pragma unroll
    for (int j = 1; j < GROUP_SZ; ++j) gm = fmaxf(gm, g_m[i0 + j]);

    float acc = 0.0f;
    float ll  = 0.0f;
    #pragma unroll 4
    for (int j = 0; j < GROUP_SZ; ++j) {
        const float sf = __expf(g_m[i0 + j] - gm);
        acc += g_part[i0 + j][t] * sf;
        ll  += g_l[i0 + j] * sf;
    }
    g_part2[grp][t] = acc;
    if (t == 0) { g_m2[grp] = gm; g_l2[grp] = ll; }

    __syncthreads();
    if (t == 0) {
        __threadfence();  // release
        s_last = (atomicAdd(&g_cnt, 1u) == NGROUPS - 1u);
    }
    __syncthreads();
    if (!s_last) return;
    if (t == 0) __threadfence();  // acquire
    __syncthreads();

    float fm = g_m2[0];
    #pragma unroll
    for (int j = 1; j < NGROUPS; ++j) fm = fmaxf(fm, g_m2[j]);

    float facc = 0.0f;
    float fll  = 0.0f;
    #pragma unroll 4
    for (int j = 0; j < NGROUPS; ++j) {
        const float sf = __expf(g_m2[j] - fm);
        facc += g_part2[j][t] * sf;
        fll  += g_l2[j] * sf;
    }
    out[t] = facc / fll;

    if (t == 0) g_cnt = 0u;   // reset for next graph replay
}

extern "C" void kernel_launch(void* const* d_in, const int* in_sizes, int n_in,
                              void* d_out, int out_size) {
    const float* q = (const float*)d_in[0];
    const float* K = (const float*)d_in[1];
    const float* V = (const float*)d_in[2];
    float* out = (float*)d_out;

    sqa_pass1<<<NCTA, 256>>>(q, K, V);
    sqa_pass2<<<NGROUPS, 256>>>(out);
}

// round 8
// speedup vs baseline: 1.1795x; 1.0501x over previous
#include <cuda_runtime.h>
#include <math_constants.h>

// Single-query attention: y = softmax(K @ q) @ V   (fp32, M=131072, D=256)
// Pass1: persistent single-wave (592 = 148 SM x 4 CTAs), 16-row chunks
// striped across CTAs. Inner body issues K AND V loads together (8 LDG.128)
// so V loads overlap the dot-product shuffle chain. Online softmax rescale.
// Tail: two flat feed-forward kernels (no last-arriver serialization):
//   A: 1 block   -> gmax, sf[i], invL
//   B: 256 blocks -> per-output-column reduction over 592 scaled partials.

#define M_TOTAL   131072
#define DIM       256
#define NCTA      592                      // 148 * 4, one wave
#define NWARPS    8
#define RB        2                        // rows per warp per chunk
#define CHUNK_ROWS (NWARPS * RB)           // 16
#define NCHUNKS   (M_TOTAL / CHUNK_ROWS)   // 8192

// Scratch (allocation-free): ~620 KB
__device__ float g_part[NCTA][DIM];
__device__ float g_m[NCTA];
__device__ float g_l[NCTA];
__device__ float g_sf[NCTA];
__device__ float g_invL;

__global__ __launch_bounds__(256, 4)
void sqa_pass1(const float* __restrict__ q,
               const float* __restrict__ K,
               const float* __restrict__ V) {
    const int tid  = threadIdx.x;
    const int warp = tid >> 5;
    const int lane = tid & 31;
    const int bid  = blockIdx.x;

    const float4 q0 = reinterpret_cast<const float4*>(q)[lane];
    const float4 q1 = reinterpret_cast<const float4*>(q)[lane + 32];

    float m = -CUDART_INF_F;
    float l = 0.0f;
    float4 a0 = make_float4(0.f, 0.f, 0.f, 0.f);
    float4 a1 = make_float4(0.f, 0.f, 0.f, 0.f);

    for (int c = bid; c < NCHUNKS; c += NCTA) {
        const int row0 = c * CHUNK_ROWS + warp * RB;
        const float4* Ka = reinterpret_cast<const float4*>(K + (size_t)row0 * DIM);
        const float4* Kb = reinterpret_cast<const float4*>(K + (size_t)(row0 + 1) * DIM);
        const float4* Va = reinterpret_cast<const float4*>(V + (size_t)row0 * DIM);
        const float4* Vb = reinterpret_cast<const float4*>(V + (size_t)(row0 + 1) * DIM);

        // 8 independent LDG.128 issued together: V loads fly during shuffles
        const float4 k0a = Ka[lane];
        const float4 k1a = Ka[lane + 32];
        const float4 k0b = Kb[lane];
        const float4 k1b = Kb[lane + 32];
        const float4 v0a = Va[lane];
        const float4 v1a = Va[lane + 32];
        const float4 v0b = Vb[lane];
        const float4 v1b = Vb[lane + 32];

        float da = k0a.x * q0.x + k0a.y * q0.y + k0a.z * q0.z + k0a.w * q0.w
                 + k1a.x * q1.x + k1a.y * q1.y + k1a.z * q1.z + k1a.w * q1.w;
        float db = k0b.x * q0.x + k0b.y * q0.y + k0b.z * q0.z + k0b.w * q0.w
                 + k1b.x * q1.x + k1b.y * q1.y + k1b.z * q1.z + k1b.w * q1.w;
        #pragma unroll
        for (int off = 16; off > 0; off >>= 1) {
            da += __shfl_xor_sync(0xffffffffu, da, off);
            db += __shfl_xor_sync(0xffffffffu, db, off);
        }

        const float mnew  = fmaxf(m, fmaxf(da, db));
        const float scale = __expf(m - mnew);   // exp(-inf)=0 on first chunk
        const float wa    = __expf(da - mnew);
        const float wb    = __expf(db - mnew);
        l = l * scale + wa + wb;
        m = mnew;

        a0.x = a0.x * scale + wa * v0a.x + wb * v0b.x;
        a0.y = a0.y * scale + wa * v0a.y + wb * v0b.y;
        a0.z = a0.z * scale + wa * v0a.z + wb * v0b.z;
        a0.w = a0.w * scale + wa * v0a.w + wb * v0b.w;
        a1.x = a1.x * scale + wa * v1a.x + wb * v1b.x;
        a1.y = a1.y * scale + wa * v1a.y + wb * v1b.y;
        a1.z = a1.z * scale + wa * v1a.z + wb * v1b.z;
        a1.w = a1.w * scale + wa * v1a.w + wb * v1b.w;
    }

    // ---------------- Merge 8 warps within the CTA ------------------------
    __shared__ float s_m[NWARPS];
    __shared__ float s_l[NWARPS];
    __shared__ float s_acc[NWARPS][DIM];

    if (lane == 0) { s_m[warp] = m; s_l[warp] = l; }
    float* dst = s_acc[warp];
    dst[lane * 4 + 0]       = a0.x;
    dst[lane * 4 + 1]       = a0.y;
    dst[lane * 4 + 2]       = a0.z;
    dst[lane * 4 + 3]       = a0.w;
    dst[128 + lane * 4 + 0] = a1.x;
    dst[128 + lane * 4 + 1] = a1.y;
    dst[128 + lane * 4 + 2] = a1.z;
    dst[128 + lane * 4 + 3] = a1.w;
    __syncthreads();

    float bm = s_m[0];
    #pragma unroll
    for (int w2 = 1; w2 < NWARPS; ++w2) bm = fmaxf(bm, s_m[w2]);

    float y = 0.0f;
    float L = 0.0f;
    #pragma unroll
    for (int w2 = 0; w2 < NWARPS; ++w2) {
        const float sf = __expf(s_m[w2] - bm);
        y += s_acc[w2][tid] * sf;
        L += s_l[w2] * sf;
    }

    g_part[bid][tid] = y;
    if (tid == 0) { g_m[bid] = bm; g_l[bid] = L; }
}

// Tail A: 1 block x 1024 threads. gmax over 592 maxes, sf[i], invL.
__global__ __launch_bounds__(1024)
void sqa_tailA() {
    __shared__ float red[1024];
    const int t = threadIdx.x;

    const bool on = (t < NCTA);
    const float mi = on ? g_m[t] : -CUDART_INF_F;
    red[t] = mi;
    __syncthreads();
    #pragma unroll
    for (int s = 512; s > 0; s >>= 1) {
        if (t < s) red[t] = fmaxf(red[t], red[t + s]);
        __syncthreads();
    }
    const float gmax = red[0];
    __syncthreads();

    float e = 0.0f;
    if (on) {
        e = __expf(mi - gmax);
        g_sf[t] = e;
    }
    red[t] = on ? g_l[t] * e : 0.0f;
    __syncthreads();
    #pragma unroll
    for (int s = 512; s > 0; s >>= 1) {
        if (t < s) red[t] += red[t + s];
        __syncthreads();
    }
    if (t == 0) g_invL = 1.0f / red[0];
}

// Tail B: 256 blocks (one per output column) x 256 threads.
// Block c reduces sum_i g_part[i][c] * g_sf[i] over i in [0,592).
__global__ __launch_bounds__(256)
void sqa_tailB(float* __restrict__ out) {
    const int t = threadIdx.x;
    const int c = blockIdx.x;

    // 3 independent strided loads per thread (592 = 2*256 + 80)
    float acc = g_part[t][c] * g_sf[t]
              + g_part[t + 256][c] * g_sf[t + 256];
    if (t < NCTA - 512)
        acc += g_part[t + 512][c] * g_sf[t + 512];

    __shared__ float red[256];
    red[t] = acc;
    __syncthreads();
    #pragma unroll
    for (int s = 128; s > 32; s >>= 1) {
        if (t < s) red[t] += red[t + s];
        __syncthreads();
    }
    if (t < 32) {
        float v = red[t] + red[t + 32];
        #pragma unroll
        for (int off = 16; off > 0; off >>= 1)
            v += __shfl_xor_sync(0xffffffffu, v, off);
        if (t == 0) out[c] = v * g_invL;
    }
}

extern "C" void kernel_launch(void* const* d_in, const int* in_sizes, int n_in,
                              void* d_out, int out_size) {
    const float* q = (const float*)d_in[0];
    const float* K = (const float*)d_in[1];
    const float* V = (const float*)d_in[2];
    float* out = (float*)d_out;

    sqa_pass1<<<NCTA, 256>>>(q, K, V);
    sqa_tailA<<<1, 1024>>>();
    sqa_tailB<<<DIM, 256>>>(out);
}

// round 9
// speedup vs baseline: 1.2126x; 1.0281x over previous
#include <cuda_runtime.h>
#include <math_constants.h>

// Single-query attention: y = softmax(K @ q) @ V   (fp32, M=131072, D=256)
// Pass1: persistent single-wave (592 = 148 SM x 4 CTAs), 32-row chunks,
// RB=4 two-phase body (K batch -> softmax -> V batch) — fastest measured
// variant (~6.8 TB/s). Tail: ONE flat kernel, 256 blocks (one per output
// column); each block redundantly computes gmax/invL (L2-hot, parallel)
// then reduces its column. No last-arriver serialization, one launch fewer.

#define M_TOTAL   131072
#define DIM       256
#define NCTA      592                      // 148 * 4, one wave
#define NWARPS    8
#define RB        4                        // rows per warp per chunk
#define CHUNK_ROWS (NWARPS * RB)           // 32
#define NCHUNKS   (M_TOTAL / CHUNK_ROWS)   // 4096

// Scratch (allocation-free): ~620 KB
__device__ float g_part[NCTA][DIM];
__device__ float g_m[NCTA];
__device__ float g_l[NCTA];

__global__ __launch_bounds__(256, 4)
void sqa_pass1(const float* __restrict__ q,
               const float* __restrict__ K,
               const float* __restrict__ V) {
    const int tid  = threadIdx.x;
    const int warp = tid >> 5;
    const int lane = tid & 31;
    const int bid  = blockIdx.x;

    const float4 q0 = reinterpret_cast<const float4*>(q)[lane];
    const float4 q1 = reinterpret_cast<const float4*>(q)[lane + 32];

    float m = -CUDART_INF_F;
    float l = 0.0f;
    float4 a0 = make_float4(0.f, 0.f, 0.f, 0.f);
    float4 a1 = make_float4(0.f, 0.f, 0.f, 0.f);

    for (int c = bid; c < NCHUNKS; c += NCTA) {
        const int row0 = c * CHUNK_ROWS + warp * RB;

        // -------- K batch: 8 independent LDG.128 --------
        float4 k0[RB], k1[RB];
        #pragma unroll
        for (int j = 0; j < RB; ++j) {
            const float4* Kr =
                reinterpret_cast<const float4*>(K + (size_t)(row0 + j) * DIM);
            k0[j] = Kr[lane];
            k1[j] = Kr[lane + 32];
        }

        float d[RB];
        #pragma unroll
        for (int j = 0; j < RB; ++j) {
            float v = k0[j].x * q0.x + k0[j].y * q0.y + k0[j].z * q0.z + k0[j].w * q0.w
                    + k1[j].x * q1.x + k1[j].y * q1.y + k1[j].z * q1.z + k1[j].w * q1.w;
            #pragma unroll
            for (int off = 16; off > 0; off >>= 1)
                v += __shfl_xor_sync(0xffffffffu, v, off);
            d[j] = v;
        }

        // -------- online softmax update (chunk granularity) --------
        float mc = fmaxf(fmaxf(d[0], d[1]), fmaxf(d[2], d[3]));
        const float mnew  = fmaxf(m, mc);
        const float scale = __expf(m - mnew);   // exp(-inf)=0 on first chunk
        float w[RB];
        #pragma unroll
        for (int j = 0; j < RB; ++j) w[j] = __expf(d[j] - mnew);
        l = l * scale + (w[0] + w[1]) + (w[2] + w[3]);
        m = mnew;

        // -------- V batch: 8 independent LDG.128, weighted accumulate -----
        float4 v0[RB], v1[RB];
        #pragma unroll
        for (int j = 0; j < RB; ++j) {
            const float4* Vr =
                reinterpret_cast<const float4*>(V + (size_t)(row0 + j) * DIM);
            v0[j] = Vr[lane];
            v1[j] = Vr[lane + 32];
        }

        a0.x *= scale; a0.y *= scale; a0.z *= scale; a0.w *= scale;
        a1.x *= scale; a1.y *= scale; a1.z *= scale; a1.w *= scale;
        #pragma unroll
        for (int j = 0; j < RB; ++j) {
            a0.x += w[j] * v0[j].x;  a0.y += w[j] * v0[j].y;
            a0.z += w[j] * v0[j].z;  a0.w += w[j] * v0[j].w;
            a1.x += w[j] * v1[j].x;  a1.y += w[j] * v1[j].y;
            a1.z += w[j] * v1[j].z;  a1.w += w[j] * v1[j].w;
        }
    }

    // ---------------- Merge 8 warps within the CTA ------------------------
    __shared__ float s_m[NWARPS];
    __shared__ float s_l[NWARPS];
    __shared__ float s_acc[NWARPS][DIM];

    if (lane == 0) { s_m[warp] = m; s_l[warp] = l; }
    float* dst = s_acc[warp];
    dst[lane * 4 + 0]       = a0.x;
    dst[lane * 4 + 1]       = a0.y;
    dst[lane * 4 + 2]       = a0.z;
    dst[lane * 4 + 3]       = a0.w;
    dst[128 + lane * 4 + 0] = a1.x;
    dst[128 + lane * 4 + 1] = a1.y;
    dst[128 + lane * 4 + 2] = a1.z;
    dst[128 + lane * 4 + 3] = a1.w;
    __syncthreads();

    float bm = s_m[0];
    #pragma unroll
    for (int w2 = 1; w2 < NWARPS; ++w2) bm = fmaxf(bm, s_m[w2]);

    float y = 0.0f;
    float L = 0.0f;
    #pragma unroll
    for (int w2 = 0; w2 < NWARPS; ++w2) {
        const float sf = __expf(s_m[w2] - bm);
        y += s_acc[w2][tid] * sf;
        L += s_l[w2] * sf;
    }

    g_part[bid][tid] = y;
    if (tid == 0) { g_m[bid] = bm; g_l[bid] = L; }
}

// Tail: 256 blocks (one per output column) x 256 threads. Each block
// redundantly computes gmax + invL from g_m/g_l (592 floats, L2-hot,
// coalesced), then reduces its column of g_part.
__global__ __launch_bounds__(256)
void sqa_tail(float* __restrict__ out) {
    const int t = threadIdx.x;
    const int c = blockIdx.x;

    __shared__ float red[256];
    __shared__ float s_sf[NCTA];
    __shared__ float s_gmax, s_invL;

    // gmax over 592 CTA maxes
    float mi = g_m[t];
    {
        const float mi2 = g_m[t + 256];
        mi = fmaxf(mi, mi2);
        if (t < NCTA - 512) mi = fmaxf(mi, g_m[t + 512]);
    }
    red[t] = mi;
    __syncthreads();
    #pragma unroll
    for (int s = 128; s > 0; s >>= 1) {
        if (t < s) red[t] = fmaxf(red[t], red[t + s]);
        __syncthreads();
    }
    if (t == 0) s_gmax = red[0];
    __syncthreads();
    const float gmax = s_gmax;

    // scale factors + global L
    float ll = 0.0f;
    {
        float e = __expf(g_m[t] - gmax);
        s_sf[t] = e;
        ll += g_l[t] * e;
        e = __expf(g_m[t + 256] - gmax);
        s_sf[t + 256] = e;
        ll += g_l[t + 256] * e;
        if (t < NCTA - 512) {
            e = __expf(g_m[t + 512] - gmax);
            s_sf[t + 512] = e;
            ll += g_l[t + 512] * e;
        }
    }
    red[t] = ll;
    __syncthreads();
    #pragma unroll
    for (int s = 128; s > 0; s >>= 1) {
        if (t < s) red[t] += red[t + s];
        __syncthreads();
    }
    if (t == 0) s_invL = 1.0f / red[0];
    __syncthreads();

    // column reduction: sum_i g_part[i][c] * sf[i]
    float acc = g_part[t][c] * s_sf[t]
              + g_part[t + 256][c] * s_sf[t + 256];
    if (t < NCTA - 512)
        acc += g_part[t + 512][c] * s_sf[t + 512];

    red[t] = acc;
    __syncthreads();
    #pragma unroll
    for (int s = 128; s > 32; s >>= 1) {
        if (t < s) red[t] += red[t + s];
        __syncthreads();
    }
    if (t < 32) {
        float v = red[t] + red[t + 32];
        #pragma unroll
        for (int off = 16; off > 0; off >>= 1)
            v += __shfl_xor_sync(0xffffffffu, v, off);
        if (t == 0) out[c] = v * s_invL;
    }
}

extern "C" void kernel_launch(void* const* d_in, const int* in_sizes, int n_in,
                              void* d_out, int out_size) {
    const float* q = (const float*)d_in[0];
    const float* K = (const float*)d_in[1];
    const float* V = (const float*)d_in[2];
    float* out = (float*)d_out;

    sqa_pass1<<<NCTA, 256>>>(q, K, V);
    sqa_tail<<<DIM, 256>>>(out);
}

// round 10
// speedup vs baseline: 1.2721x; 1.0491x over previous
#include <cuda_runtime.h>
#include <math_constants.h>

// Single-query attention: y = softmax(K @ q) @ V   (fp32, M=131072, D=256)
// Pass1: persistent single-wave (592 = 148 SM x 4 CTAs), 32-row chunks,
// RB=4 two-phase body (K batch -> softmax -> V batch). Measured ~6.5-6.7TB/s
// = chip LTS cap (path-independent ~6300 B/cyc); treated as the floor.
// Partials stored TRANSPOSED so the tail reads coalesced rows.
// Tail: one flat kernel, 256 blocks (one per output column), shfl-based
// reductions (2 syncs each), sf factors kept in registers.

#define M_TOTAL   131072
#define DIM       256
#define NCTA      592                      // 148 * 4, one wave
#define NWARPS    8
#define RB        4                        // rows per warp per chunk
#define CHUNK_ROWS (NWARPS * RB)           // 32
#define NCHUNKS   (M_TOTAL / CHUNK_ROWS)   // 4096

// Scratch (allocation-free): ~620 KB
__device__ float g_partT[DIM][NCTA];       // transposed: [column][cta]
__device__ float g_m[NCTA];
__device__ float g_l[NCTA];

__global__ __launch_bounds__(256, 4)
void sqa_pass1(const float* __restrict__ q,
               const float* __restrict__ K,
               const float* __restrict__ V) {
    const int tid  = threadIdx.x;
    const int warp = tid >> 5;
    const int lane = tid & 31;
    const int bid  = blockIdx.x;

    const float4 q0 = reinterpret_cast<const float4*>(q)[lane];
    const float4 q1 = reinterpret_cast<const float4*>(q)[lane + 32];

    float m = -CUDART_INF_F;
    float l = 0.0f;
    float4 a0 = make_float4(0.f, 0.f, 0.f, 0.f);
    float4 a1 = make_float4(0.f, 0.f, 0.f, 0.f);

    for (int c = bid; c < NCHUNKS; c += NCTA) {
        const int row0 = c * CHUNK_ROWS + warp * RB;

        // -------- K batch: 8 independent LDG.128 --------
        float4 k0[RB], k1[RB];
        #pragma unroll
        for (int j = 0; j < RB; ++j) {
            const float4* Kr =
                reinterpret_cast<const float4*>(K + (size_t)(row0 + j) * DIM);
            k0[j] = Kr[lane];
            k1[j] = Kr[lane + 32];
        }

        float d[RB];
        #pragma unroll
        for (int j = 0; j < RB; ++j) {
            float v = k0[j].x * q0.x + k0[j].y * q0.y + k0[j].z * q0.z + k0[j].w * q0.w
                    + k1[j].x * q1.x + k1[j].y * q1.y + k1[j].z * q1.z + k1[j].w * q1.w;
            #pragma unroll
            for (int off = 16; off > 0; off >>= 1)
                v += __shfl_xor_sync(0xffffffffu, v, off);
            d[j] = v;
        }

        // -------- online softmax update (chunk granularity) --------
        float mc = fmaxf(fmaxf(d[0], d[1]), fmaxf(d[2], d[3]));
        const float mnew  = fmaxf(m, mc);
        const float scale = __expf(m - mnew);   // exp(-inf)=0 on first chunk
        float w[RB];
        #pragma unroll
        for (int j = 0; j < RB; ++j) w[j] = __expf(d[j] - mnew);
        l = l * scale + (w[0] + w[1]) + (w[2] + w[3]);
        m = mnew;

        // -------- V batch: 8 independent LDG.128, weighted accumulate -----
        float4 v0[RB], v1[RB];
        #pragma unroll
        for (int j = 0; j < RB; ++j) {
            const float4* Vr =
                reinterpret_cast<const float4*>(V + (size_t)(row0 + j) * DIM);
            v0[j] = Vr[lane];
            v1[j] = Vr[lane + 32];
        }

        a0.x *= scale; a0.y *= scale; a0.z *= scale; a0.w *= scale;
        a1.x *= scale; a1.y *= scale; a1.z *= scale; a1.w *= scale;
        #pragma unroll
        for (int j = 0; j < RB; ++j) {
            a0.x += w[j] * v0[j].x;  a0.y += w[j] * v0[j].y;
            a0.z += w[j] * v0[j].z;  a0.w += w[j] * v0[j].w;
            a1.x += w[j] * v1[j].x;  a1.y += w[j] * v1[j].y;
            a1.z += w[j] * v1[j].z;  a1.w += w[j] * v1[j].w;
        }
    }

    // ---------------- Merge 8 warps within the CTA ------------------------
    __shared__ float s_m[NWARPS];
    __shared__ float s_l[NWARPS];
    __shared__ float s_acc[NWARPS][DIM];

    if (lane == 0) { s_m[warp] = m; s_l[warp] = l; }
    float* dst = s_acc[warp];
    dst[lane * 4 + 0]       = a0.x;
    dst[lane * 4 + 1]       = a0.y;
    dst[lane * 4 + 2]       = a0.z;
    dst[lane * 4 + 3]       = a0.w;
    dst[128 + lane * 4 + 0] = a1.x;
    dst[128 + lane * 4 + 1] = a1.y;
    dst[128 + lane * 4 + 2] = a1.z;
    dst[128 + lane * 4 + 3] = a1.w;
    __syncthreads();

    float bm = s_m[0];
    #pragma unroll
    for (int w2 = 1; w2 < NWARPS; ++w2) bm = fmaxf(bm, s_m[w2]);

    float y = 0.0f;
    float L = 0.0f;
    #pragma unroll
    for (int w2 = 0; w2 < NWARPS; ++w2) {
        const float sf = __expf(s_m[w2] - bm);
        y += s_acc[w2][tid] * sf;
        L += s_l[w2] * sf;
    }

    // Transposed store: scattered 4B stores (hidden), coalesced tail reads.
    g_partT[tid][bid] = y;
    if (tid == 0) { g_m[bid] = bm; g_l[bid] = L; }
}

// Block reduction helpers: shfl within warp, one smem round across 8 warps.
__device__ __forceinline__ float blk_max(float v, float* s8, int warp, int lane) {
    #pragma unroll
    for (int off = 16; off > 0; off >>= 1)
        v = fmaxf(v, __shfl_xor_sync(0xffffffffu, v, off));
    if (lane == 0) s8[warp] = v;
    __syncthreads();
    float r = fmaxf(fmaxf(fmaxf(s8[0], s8[1]), fmaxf(s8[2], s8[3])),
                    fmaxf(fmaxf(s8[4], s8[5]), fmaxf(s8[6], s8[7])));
    __syncthreads();
    return r;
}

__device__ __forceinline__ float blk_sum(float v, float* s8, int warp, int lane) {
    #pragma unroll
    for (int off = 16; off > 0; off >>= 1)
        v += __shfl_xor_sync(0xffffffffu, v, off);
    if (lane == 0) s8[warp] = v;
    __syncthreads();
    float r = ((s8[0] + s8[1]) + (s8[2] + s8[3]))
            + ((s8[4] + s8[5]) + (s8[6] + s8[7]));
    __syncthreads();
    return r;
}

// Tail: 256 blocks (one per output column) x 256 threads. Prefix (gmax,
// invL) computed redundantly per block from L2-hot g_m/g_l; column reads
// fully coalesced thanks to the transposed partial layout.
__global__ __launch_bounds__(256)
void sqa_tail(float* __restrict__ out) {
    const int t    = threadIdx.x;
    const int warp = t >> 5;
    const int lane = t & 31;
    const int c    = blockIdx.x;

    __shared__ float s8[NWARPS];

    // load m (and later l) for indices t, t+256, t+512(partial)
    const bool has3 = (t < NCTA - 512);
    const float m0 = g_m[t];
    const float m1 = g_m[t + 256];
    const float m2 = has3 ? g_m[t + 512] : -CUDART_INF_F;

    const float gmax = blk_max(fmaxf(fmaxf(m0, m1), m2), s8, warp, lane);

    // scale factors stay in registers
    const float e0 = __expf(m0 - gmax);
    const float e1 = __expf(m1 - gmax);
    const float e2 = has3 ? __expf(m2 - gmax) : 0.0f;

    float ll = g_l[t] * e0 + g_l[t + 256] * e1;
    if (has3) ll += g_l[t + 512] * e2;
    const float invL = 1.0f / blk_sum(ll, s8, warp, lane);

    // coalesced column reduction over g_partT[c][*]
    const float* row = g_partT[c];
    float acc = row[t] * e0 + row[t + 256] * e1;
    if (has3) acc += row[t + 512] * e2;

    #pragma unroll
    for (int off = 16; off > 0; off >>= 1)
        acc += __shfl_xor_sync(0xffffffffu, acc, off);
    if (lane == 0) s8[warp] = acc;
    __syncthreads();
    if (t == 0) {
        const float v = ((s8[0] + s8[1]) + (s8[2] + s8[3]))
                      + ((s8[4] + s8[5]) + (s8[6] + s8[7]));
        out[c] = v * invL;
    }
}

extern "C" void kernel_launch(void* const* d_in, const int* in_sizes, int n_in,
                              void* d_out, int out_size) {
    const float* q = (const float*)d_in[0];
    const float* K = (const float*)d_in[1];
    const float* V = (const float*)d_in[2];
    float* out = (float*)d_out;

    sqa_pass1<<<NCTA, 256>>>(q, K, V);
    sqa_tail<<<DIM, 256>>>(out);
}